// round 8
// baseline (speedup 1.0000x reference)
#include <cuda_runtime.h>
#include <cstdint>

// Problem constants
#define B_ 64
#define L_ 512
#define P_ 64
#define A_ 16
#define F_ 80
#define D_ 512

// Scan organization
#define CSZ 8       // CTAs per cluster (column split of R)
#define NCL 16      // clusters (B_/ROWS)
#define ROWS 4      // batch rows per cluster
#define COLS 64     // columns per CTA
#define KROWS 32    // rows per warp k-slice (16 warps)
#define THREADS 512

// Scratch
__device__ float g_ci[B_ * L_ * D_];      // tanh(x@W_ci+b)
__device__ float g_part[B_ * CSZ * L_];   // per-CTA cumulative output partials

// ---- f32x2 helpers --------------------------------------------------------
__device__ __forceinline__ unsigned long long pk2(float lo, float hi) {
    unsigned long long r;
    asm("mov.b64 %0, {%1,%2};" : "=l"(r) : "f"(lo), "f"(hi));
    return r;
}
__device__ __forceinline__ void fma2(unsigned long long& d, unsigned long long a, unsigned long long b) {
    asm("fma.rn.f32x2 %0, %1, %2, %0;" : "+l"(d) : "l"(a), "l"(b));
}
__device__ __forceinline__ float hadd2(unsigned long long v) {
    float lo, hi;
    asm("mov.b64 {%0,%1}, %2;" : "=f"(lo), "=f"(hi) : "l"(v));
    return lo + hi;
}

// ---- mbarrier / bulk-DSMEM helpers ----------------------------------------
__device__ __forceinline__ void mbar_init(uint32_t addr, uint32_t cnt) {
    asm volatile("mbarrier.init.shared.b64 [%0], %1;" :: "r"(addr), "r"(cnt) : "memory");
}
__device__ __forceinline__ void mbar_expect_tx(uint32_t addr, uint32_t bytes) {
    asm volatile("mbarrier.arrive.expect_tx.shared.b64 _, [%0], %1;"
                 :: "r"(addr), "r"(bytes) : "memory");
}
__device__ __forceinline__ void mbar_wait_cta(uint32_t addr, uint32_t parity) {
    uint32_t done;
    asm volatile(
        "{\n\t.reg .pred p;\n\t"
        "mbarrier.try_wait.parity.acquire.cta.shared::cta.b64 p, [%1], %2;\n\t"
        "selp.b32 %0, 1, 0, p;\n\t}"
        : "=r"(done) : "r"(addr), "r"(parity) : "memory");
    if (!done) {
        asm volatile(
            "{\n\t.reg .pred P1;\n\t"
            "WL_%=:\n\t"
            "mbarrier.try_wait.parity.acquire.cta.shared::cta.b64 P1, [%0], %1, 0x989680;\n\t"
            "@P1 bra.uni WD_%=;\n\t"
            "bra.uni WL_%=;\n\t"
            "WD_%=:\n\t}"
            :: "r"(addr), "r"(parity) : "memory");
    }
}
__device__ __forceinline__ void bulk_dsmem(uint32_t dst, uint32_t src,
                                           uint32_t bytes, uint32_t mbar) {
    asm volatile(
        "cp.async.bulk.shared::cluster.shared::cta.mbarrier::complete_tx::bytes "
        "[%0], [%1], %2, [%3];"
        :: "r"(dst), "r"(src), "r"(bytes), "r"(mbar) : "memory");
}
__device__ __forceinline__ void fence_proxy_async_cta() {
    asm volatile("fence.proxy.async.shared::cta;" ::: "memory");
}

// ============================================================================
// Kernel 1: ci = tanh(x @ W_ci + b_ci)
// ============================================================================
__global__ __launch_bounds__(256)
void k_ci(const float* __restrict__ obs, const float* __restrict__ act,
          const float* __restrict__ W, const float* __restrict__ bci)
{
    __shared__ float xs[64][81];
    __shared__ float ws[80][64];

    const int tid  = threadIdx.x;
    const int row0 = blockIdx.y * 64;
    const int d0   = blockIdx.x * 64;

    for (int idx = tid; idx < 64 * 80; idx += 256) {
        int r = idx / 80, c = idx % 80;
        int blg = row0 + r;
        int b = blg >> 9, l = blg & 511;
        xs[r][c] = (c < 64) ? obs[(b * L_ + l) * P_ + c]
                            : act[(b * L_ + l) * A_ + (c - 64)];
    }
    for (int idx = tid; idx < 80 * 64; idx += 256) {
        int k = idx >> 6, d = idx & 63;
        ws[k][d] = W[k * D_ + d0 + d];
    }
    __syncthreads();

    const int tx = tid & 15, ty = tid >> 4;
    float acc[4][4] = {};
#pragma unroll
    for (int k = 0; k < 80; k++) {
        float a0 = xs[ty * 4 + 0][k];
        float a1 = xs[ty * 4 + 1][k];
        float a2 = xs[ty * 4 + 2][k];
        float a3 = xs[ty * 4 + 3][k];
        float4 bv = *(const float4*)&ws[k][tx * 4];
        acc[0][0] += a0 * bv.x; acc[0][1] += a0 * bv.y; acc[0][2] += a0 * bv.z; acc[0][3] += a0 * bv.w;
        acc[1][0] += a1 * bv.x; acc[1][1] += a1 * bv.y; acc[1][2] += a1 * bv.z; acc[1][3] += a1 * bv.w;
        acc[2][0] += a2 * bv.x; acc[2][1] += a2 * bv.y; acc[2][2] += a2 * bv.z; acc[2][3] += a2 * bv.w;
        acc[3][0] += a3 * bv.x; acc[3][1] += a3 * bv.y; acc[3][2] += a3 * bv.z; acc[3][3] += a3 * bv.w;
    }

    float bi0 = bci[d0 + tx * 4 + 0];
    float bi1 = bci[d0 + tx * 4 + 1];
    float bi2 = bci[d0 + tx * 4 + 2];
    float bi3 = bci[d0 + tx * 4 + 3];
#pragma unroll
    for (int ii = 0; ii < 4; ii++) {
        int blg = row0 + ty * 4 + ii;
        float4 o;
        o.x = tanhf(acc[ii][0] + bi0);
        o.y = tanhf(acc[ii][1] + bi1);
        o.z = tanhf(acc[ii][2] + bi2);
        o.w = tanhf(acc[ii][3] + bi3);
        *(float4*)&g_ci[blg * D_ + d0 + tx * 4] = o;
    }
}

// ============================================================================
// Kernel 2: the scan.
//  - h stored BATCH-MAJOR: hbuf[buf][b][i] (4 vectors of 512 floats)
//  - R pre-packed as row-pair registers per column (built once; no per-iter MOVs)
//  - matvec chunk (4 rows): 4 LDS.128 + 16 FFMA2  => FMA-pipe-bound
//  - per-(buffer,source) barriers: warp starts when ITS source slice arrives
//  - DMA: 32 x 256 B bulk copies per step (payload unchanged vs best kernel)
//
// SMEM (floats):
//   hbuf [0, 6144)        3 x 4 x 512
//   pbuf [6144, 10240)    512 x 8
//   hsta [10240, 10752)   2 x 4 x 64  (DMA source, per-parity, batch-major)
//   bias [10752, 10816)
//   wsl  [10816, 10880)
//   osum [10880, 10912)
//   mbar @ byte 43648: 3 bufs x 8 sources x 8 B
// ============================================================================
#define HBUF_OFF  0
#define PBUF_OFF  6144
#define HSTA_OFF  10240
#define BIAS_OFF  10752
#define WSL_OFF   10816
#define OSUM_OFF  10880
#define MBAR_BYTE 43648
#define SMEM_BYTES (MBAR_BYTE + 192)

#define CHUNK_BYTES 256                   // 64 floats: one (source, batch) piece
#define SRC_TX      1024                  // 4 batch chunks per source per round

extern __shared__ float smem_f[];

__global__ void __cluster_dims__(CSZ, 1, 1) __launch_bounds__(THREADS, 1)
k_scan(const float* __restrict__ R, const float* __restrict__ b_ig,
       const float* __restrict__ W_out)
{
    float* hbuf = smem_f + HBUF_OFF;
    float* pbuf = smem_f + PBUF_OFF;
    float* hsta = smem_f + HSTA_OFF;
    float* bias = smem_f + BIAS_OFF;
    float* wsl  = smem_f + WSL_OFF;
    float* osum = smem_f + OSUM_OFF;

    const uint32_t smem_u32 = (uint32_t)__cvta_generic_to_shared(smem_f);

    const int tid = threadIdx.x;
    const int c   = blockIdx.x;          // cluster rank / column slice
    const int b0  = blockIdx.y * ROWS;
    const int j0  = c * COLS;

    const int ks   = tid >> 5;           // warp = k-slice (rows ks*32..+32)
    const int jp   = tid & 31;           // cols 2jp, 2jp+1
    const int lane = tid & 31;
    const int src  = ks >> 1;            // source CTA feeding this warp's rows
    const int jj = tid >> 2;             // reduce mapping (tid<256)
    const int bb = tid & 3;

    // ---- R row-pairs packed into registers: rp0/rp1 for cols 2jp / 2jp+1 ----
    unsigned long long rp0[16], rp1[16];
    {
        const float* rg = R + j0 + 2 * jp;
#pragma unroll
        for (int ii = 0; ii < 16; ii++) {
            const float* r0 = rg + (ks * KROWS + 2 * ii) * D_;
            const float* r1 = r0 + D_;
            rp0[ii] = pk2(r0[0], r1[0]);
            rp1[ii] = pk2(r0[1], r1[1]);
        }
    }

    // ---- init smem ----
    for (int idx = tid; idx < 3 * 4 * D_; idx += THREADS) hbuf[idx] = 0.0f;
    if (tid < COLS) {
        bias[tid] = b_ig[j0 + tid];
        wsl[tid]  = W_out[j0 + tid];
    }
    if (tid < 24) {   // 3 buffers x 8 sources
        mbar_init(smem_u32 + MBAR_BYTE + tid * 8, 1);
    }
    __syncthreads();
    if (tid < 24) {
        mbar_expect_tx(smem_u32 + MBAR_BYTE + tid * 8, SRC_TX);
    }
    __syncthreads();
    asm volatile("barrier.cluster.arrive.aligned;" ::: "memory");
    asm volatile("barrier.cluster.wait.aligned;"   ::: "memory");

    float racc = 0.0f;
    int cur = 0;
    uint32_t phases = 0;   // bit b = next wait parity for buffer b

    for (int t = 0; t < L_; t++) {
        const int nxt = (cur == 2) ? 0 : cur + 1;

        // prefetch ci (consumed after matvec)
        float civ = 0.0f;
        if (tid < 256)
            civ = __ldg(&g_ci[((b0 + bb) * L_ + t) * D_ + j0 + jj]);

        // per-warp wait: only this warp's source slice must have arrived
        if (t > 0) {
            uint32_t mb = smem_u32 + (uint32_t)(MBAR_BYTE + (cur * CSZ + src) * 8);
            mbar_wait_cta(mb, (phases >> cur) & 1u);
            phases ^= (1u << cur);
            if (lane == 0 && (ks & 1) == 0)
                mbar_expect_tx(mb, SRC_TX);
        }

        // ---- matvec: packed-R regs x batch-major h (zero per-iter packing) ----
        {
            const float* hb = hbuf + cur * (4 * D_) + ks * KROWS;
            unsigned long long a00 = 0, a01 = 0, a02 = 0, a03 = 0;
            unsigned long long a10 = 0, a11 = 0, a12 = 0, a13 = 0;
#pragma unroll
            for (int ch = 0; ch < 8; ch++) {     // 4 rows per chunk
                ulonglong2 v0 = *(const ulonglong2*)(hb + 0 * D_ + ch * 4);
                ulonglong2 v1 = *(const ulonglong2*)(hb + 1 * D_ + ch * 4);
                ulonglong2 v2 = *(const ulonglong2*)(hb + 2 * D_ + ch * 4);
                ulonglong2 v3 = *(const ulonglong2*)(hb + 3 * D_ + ch * 4);
                unsigned long long p0 = rp0[2 * ch], p0b = rp0[2 * ch + 1];
                unsigned long long p1 = rp1[2 * ch], p1b = rp1[2 * ch + 1];
                fma2(a00, v0.x, p0); fma2(a00, v0.y, p0b);
                fma2(a01, v1.x, p0); fma2(a01, v1.y, p0b);
                fma2(a02, v2.x, p0); fma2(a02, v2.y, p0b);
                fma2(a03, v3.x, p0); fma2(a03, v3.y, p0b);
                fma2(a10, v0.x, p1); fma2(a10, v0.y, p1b);
                fma2(a11, v1.x, p1); fma2(a11, v1.y, p1b);
                fma2(a12, v2.x, p1); fma2(a12, v2.y, p1b);
                fma2(a13, v3.x, p1); fma2(a13, v3.y, p1b);
            }
            float4 q0, q1;
            q0.x = hadd2(a00); q0.y = hadd2(a01);
            q0.z = hadd2(a02); q0.w = hadd2(a03);
            q1.x = hadd2(a10); q1.y = hadd2(a11);
            q1.z = hadd2(a12); q1.w = hadd2(a13);
            float* pb = pbuf + (ks * 32 + jp) * 8;
            *(float4*)(pb)     = q0;   // col 2jp,   b0..b3
            *(float4*)(pb + 4) = q1;   // col 2jp+1, b0..b3
        }
        __syncthreads();

        // ---- reduce + gate + update ----
        if (tid < 256) {
            float z = bias[jj];
#pragma unroll
            for (int s = 0; s < 16; s++) z += pbuf[s * 256 + tid];
            float ig = 1.0f / (1.0f + __expf(-z));
            float u  = civ * ig;
            float hval = hbuf[cur * (4 * D_) + bb * D_ + j0 + jj] + u;
            hsta[(t & 1) * 256 + bb * 64 + jj] = hval;

            float pp = u * wsl[jj];
            pp += __shfl_xor_sync(0xFFFFFFFF, pp, 4);
            pp += __shfl_xor_sync(0xFFFFFFFF, pp, 8);
            pp += __shfl_xor_sync(0xFFFFFFFF, pp, 16);
            if ((tid & 31) < 4)
                osum[(tid >> 5) * 4 + bb] = pp;
        }
        __syncthreads();

        // ---- DMA broadcast h(t+1): 32 copies of 256 B (peer p, batch b) ----
        if (t + 1 < L_ && tid < 32) {
            fence_proxy_async_cta();
            int p = tid >> 2, b = tid & 3;
            uint32_t pb_addr;
            asm volatile("mapa.shared::cluster.u32 %0, %1, %2;"
                         : "=r"(pb_addr) : "r"(smem_u32), "r"(p));
            uint32_t src_a = smem_u32
                           + (uint32_t)(HSTA_OFF + (t & 1) * 256 + b * 64) * 4u;
            uint32_t dst   = pb_addr
                           + (uint32_t)(HBUF_OFF + nxt * (4 * D_) + b * D_) * 4u
                           + (uint32_t)(c * CHUNK_BYTES);
            uint32_t mbar  = pb_addr + (uint32_t)(MBAR_BYTE + (nxt * CSZ + c) * 8);
            bulk_dsmem(dst, src_a, CHUNK_BYTES, mbar);
        }

        // ---- cumulative output partial ----
        if (tid < 4) {
            float s = 0.0f;
#pragma unroll
            for (int w = 0; w < 8; w++) s += osum[w * 4 + tid];
            racc += s;
            g_part[(b0 + tid) * (CSZ * L_) + c * L_ + t] = racc;
        }

        cur = nxt;
    }

    asm volatile("barrier.cluster.arrive.aligned;" ::: "memory");
    asm volatile("barrier.cluster.wait.aligned;"   ::: "memory");
}

// ============================================================================
// Kernel 3: out[b,t] = b_out + sum_c g_part[b][c][t]
// ============================================================================
__global__ __launch_bounds__(256)
void k_out(const float* __restrict__ b_out, float* __restrict__ out)
{
    int i = blockIdx.x * 256 + threadIdx.x;
    int b = i >> 9, t = i & 511;
    float s = b_out[0];
#pragma unroll
    for (int cc = 0; cc < CSZ; cc++) s += g_part[b * (CSZ * L_) + cc * L_ + t];
    out[i] = s;
}

// ============================================================================
extern "C" void kernel_launch(void* const* d_in, const int* in_sizes, int n_in,
                              void* d_out, int out_size)
{
    const float* obs  = (const float*)d_in[0];
    const float* act  = (const float*)d_in[1];
    const float* W_ci = (const float*)d_in[2];
    const float* b_ci = (const float*)d_in[3];
    const float* R    = (const float*)d_in[4];
    const float* bg   = (const float*)d_in[5];
    const float* W_o  = (const float*)d_in[6];
    const float* b_o  = (const float*)d_in[7];
    float* out = (float*)d_out;

    k_ci<<<dim3(8, 512), 256>>>(obs, act, W_ci, b_ci);

    cudaFuncSetAttribute(k_scan, cudaFuncAttributeMaxDynamicSharedMemorySize, SMEM_BYTES);
    k_scan<<<dim3(CSZ, NCL), THREADS, SMEM_BYTES>>>(R, bg, W_o);

    k_out<<<128, 256>>>(b_o, out);
}

// round 10
// speedup vs baseline: 1.2420x; 1.2420x over previous
#include <cuda_runtime.h>
#include <cstdint>

// Problem constants
#define B_ 64
#define L_ 512
#define P_ 64
#define A_ 16
#define F_ 80
#define D_ 512

// Scan organization
#define CSZ 8       // CTAs per cluster (column split of R)
#define NCL 16      // clusters (B_/ROWS)
#define ROWS 4      // batch rows per cluster
#define COLS 64     // columns per CTA
#define KROWS 32    // rows per warp k-slice (16 warps)
#define THREADS 512

// Scratch
__device__ float g_ci[B_ * L_ * D_];      // tanh(x@W_ci+b)
__device__ float g_part[B_ * CSZ * L_];   // per-CTA cumulative output partials

// ---- f32x2 helpers --------------------------------------------------------
__device__ __forceinline__ unsigned long long pk2(float lo, float hi) {
    unsigned long long r;
    asm("mov.b64 %0, {%1,%2};" : "=l"(r) : "f"(lo), "f"(hi));
    return r;
}
__device__ __forceinline__ void fma2(unsigned long long& d, unsigned long long a, unsigned long long b) {
    asm("fma.rn.f32x2 %0, %1, %2, %0;" : "+l"(d) : "l"(a), "l"(b));
}
__device__ __forceinline__ void upk2(float& lo, float& hi, unsigned long long v) {
    asm("mov.b64 {%0,%1}, %2;" : "=f"(lo), "=f"(hi) : "l"(v));
}

// ---- mbarrier / bulk-DSMEM helpers ----------------------------------------
__device__ __forceinline__ void mbar_init(uint32_t addr, uint32_t cnt) {
    asm volatile("mbarrier.init.shared.b64 [%0], %1;" :: "r"(addr), "r"(cnt) : "memory");
}
__device__ __forceinline__ void mbar_expect_tx(uint32_t addr, uint32_t bytes) {
    asm volatile("mbarrier.arrive.expect_tx.shared.b64 _, [%0], %1;"
                 :: "r"(addr), "r"(bytes) : "memory");
}
__device__ __forceinline__ void mbar_wait_cta(uint32_t addr, uint32_t parity) {
    uint32_t done;
    asm volatile(
        "{\n\t.reg .pred p;\n\t"
        "mbarrier.try_wait.parity.acquire.cta.shared::cta.b64 p, [%1], %2;\n\t"
        "selp.b32 %0, 1, 0, p;\n\t}"
        : "=r"(done) : "r"(addr), "r"(parity) : "memory");
    if (!done) {
        asm volatile(
            "{\n\t.reg .pred P1;\n\t"
            "WL_%=:\n\t"
            "mbarrier.try_wait.parity.acquire.cta.shared::cta.b64 P1, [%0], %1, 0x989680;\n\t"
            "@P1 bra.uni WD_%=;\n\t"
            "bra.uni WL_%=;\n\t"
            "WD_%=:\n\t}"
            :: "r"(addr), "r"(parity) : "memory");
    }
}
__device__ __forceinline__ void bulk_dsmem(uint32_t dst, uint32_t src,
                                           uint32_t bytes, uint32_t mbar) {
    asm volatile(
        "cp.async.bulk.shared::cluster.shared::cta.mbarrier::complete_tx::bytes "
        "[%0], [%1], %2, [%3];"
        :: "r"(dst), "r"(src), "r"(bytes), "r"(mbar) : "memory");
}
__device__ __forceinline__ void fence_proxy_async_cta() {
    asm volatile("fence.proxy.async.shared::cta;" ::: "memory");
}

// ============================================================================
// Kernel 1: ci = tanh(x @ W_ci + b_ci)
// ============================================================================
__global__ __launch_bounds__(256)
void k_ci(const float* __restrict__ obs, const float* __restrict__ act,
          const float* __restrict__ W, const float* __restrict__ bci)
{
    __shared__ float xs[64][81];
    __shared__ float ws[80][64];

    const int tid  = threadIdx.x;
    const int row0 = blockIdx.y * 64;
    const int d0   = blockIdx.x * 64;

    for (int idx = tid; idx < 64 * 80; idx += 256) {
        int r = idx / 80, c = idx % 80;
        int blg = row0 + r;
        int b = blg >> 9, l = blg & 511;
        xs[r][c] = (c < 64) ? obs[(b * L_ + l) * P_ + c]
                            : act[(b * L_ + l) * A_ + (c - 64)];
    }
    for (int idx = tid; idx < 80 * 64; idx += 256) {
        int k = idx >> 6, d = idx & 63;
        ws[k][d] = W[k * D_ + d0 + d];
    }
    __syncthreads();

    const int tx = tid & 15, ty = tid >> 4;
    float acc[4][4] = {};
#pragma unroll
    for (int k = 0; k < 80; k++) {
        float a0 = xs[ty * 4 + 0][k];
        float a1 = xs[ty * 4 + 1][k];
        float a2 = xs[ty * 4 + 2][k];
        float a3 = xs[ty * 4 + 3][k];
        float4 bv = *(const float4*)&ws[k][tx * 4];
        acc[0][0] += a0 * bv.x; acc[0][1] += a0 * bv.y; acc[0][2] += a0 * bv.z; acc[0][3] += a0 * bv.w;
        acc[1][0] += a1 * bv.x; acc[1][1] += a1 * bv.y; acc[1][2] += a1 * bv.z; acc[1][3] += a1 * bv.w;
        acc[2][0] += a2 * bv.x; acc[2][1] += a2 * bv.y; acc[2][2] += a2 * bv.z; acc[2][3] += a2 * bv.w;
        acc[3][0] += a3 * bv.x; acc[3][1] += a3 * bv.y; acc[3][2] += a3 * bv.z; acc[3][3] += a3 * bv.w;
    }

    float bi0 = bci[d0 + tx * 4 + 0];
    float bi1 = bci[d0 + tx * 4 + 1];
    float bi2 = bci[d0 + tx * 4 + 2];
    float bi3 = bci[d0 + tx * 4 + 3];
#pragma unroll
    for (int ii = 0; ii < 4; ii++) {
        int blg = row0 + ty * 4 + ii;
        float4 o;
        o.x = tanhf(acc[ii][0] + bi0);
        o.y = tanhf(acc[ii][1] + bi1);
        o.z = tanhf(acc[ii][2] + bi2);
        o.w = tanhf(acc[ii][3] + bi3);
        *(float4*)&g_ci[blg * D_ + d0 + tx * 4] = o;
    }
}

// ============================================================================
// Kernel 2: the scan — R6 sync topology (ONE barrier per buffer, full-CTA
// wait, tid==256 re-post), with two local changes:
//   (a) no staging buffer: reducers write h(t+1) own slice into hbuf[nxt];
//       DMA sources it directly and skips the self-copy (7 x 1 KB, TX=7168)
//   (b) output-partial accumulation deferred to next iteration (pre-wait)
//
// SMEM (floats):
//   hbuf [0, 6144)        3 x 512 x 4   (h[i][b] interleaved)
//   pbuf [6144, 10240)    512 x 8
//   bias [10240, 10304)
//   wsl  [10304, 10368)
//   osum [10368, 10400)
//   mbar @ byte 41600 (3 x 8 B)
// ============================================================================
#define HBUF_OFF  0
#define PBUF_OFF  6144
#define BIAS_OFF  10240
#define WSL_OFF   10304
#define OSUM_OFF  10368
#define MBAR_BYTE 41600
#define SMEM_BYTES (MBAR_BYTE + 64)

#define SLICE_BYTES 1024                       // 64 cols x 4 batches x 4 B
#define STEP_TX     ((CSZ - 1) * SLICE_BYTES)  // 7168 (self-copy skipped)

extern __shared__ float smem_f[];

__global__ void __cluster_dims__(CSZ, 1, 1) __launch_bounds__(THREADS, 1)
k_scan(const float* __restrict__ R, const float* __restrict__ b_ig,
       const float* __restrict__ W_out)
{
    float* hbuf = smem_f + HBUF_OFF;
    float* pbuf = smem_f + PBUF_OFF;
    float* bias = smem_f + BIAS_OFF;
    float* wsl  = smem_f + WSL_OFF;
    float* osum = smem_f + OSUM_OFF;

    const uint32_t smem_u32 = (uint32_t)__cvta_generic_to_shared(smem_f);

    const int tid = threadIdx.x;
    const int c   = blockIdx.x;          // cluster rank / column slice
    const int b0  = blockIdx.y * ROWS;
    const int j0  = c * COLS;

    const int ks = tid >> 5;             // warp = k-slice (0..15)
    const int jp = tid & 31;             // cols 2jp, 2jp+1
    const int jj = tid >> 2;             // reduce mapping (tid<256)
    const int bb = tid & 3;

    // ---- R slice into registers (R6 layout) ----
    float rx[KROWS], ry[KROWS];
    {
        const float* rg = R + j0 + 2 * jp;
#pragma unroll
        for (int ii = 0; ii < KROWS; ii++) {
            float2 v = *(const float2*)(rg + (ks * KROWS + ii) * D_);
            rx[ii] = v.x; ry[ii] = v.y;
        }
    }

    // ---- init smem ----
    for (int idx = tid; idx < 3 * D_ * ROWS; idx += THREADS) hbuf[idx] = 0.0f;
    if (tid < COLS) {
        bias[tid] = b_ig[j0 + tid];
        wsl[tid]  = W_out[j0 + tid];
    }
    if (tid < 32) osum[tid] = 0.0f;
    if (tid == 0) {
        mbar_init(smem_u32 + MBAR_BYTE + 0,  1);
        mbar_init(smem_u32 + MBAR_BYTE + 8,  1);
        mbar_init(smem_u32 + MBAR_BYTE + 16, 1);
    }
    __syncthreads();
    if (tid == 0) {
        mbar_expect_tx(smem_u32 + MBAR_BYTE + 0,  STEP_TX);
        mbar_expect_tx(smem_u32 + MBAR_BYTE + 8,  STEP_TX);
        mbar_expect_tx(smem_u32 + MBAR_BYTE + 16, STEP_TX);
    }
    __syncthreads();
    asm volatile("barrier.cluster.arrive.aligned;" ::: "memory");
    asm volatile("barrier.cluster.wait.aligned;"   ::: "memory");

    // Peer smem bases
    uint32_t peer_base[CSZ];
#pragma unroll
    for (int p = 0; p < CSZ; p++) {
        asm volatile("mapa.shared::cluster.u32 %0, %1, %2;"
                     : "=r"(peer_base[p]) : "r"(smem_u32), "r"(p));
    }

    float racc = 0.0f;
    int cur = 0;
    uint32_t phases = 0;   // bit b = next wait parity for buffer b

    for (int t = 0; t < L_; t++) {
        const int nxt = (cur == 2) ? 0 : cur + 1;

        // prefetch ci (consumed after matvec)
        float civ = 0.0f;
        if (tid < 256)
            civ = __ldg(&g_ci[((b0 + bb) * L_ + t) * D_ + j0 + jj]);

        // deferred output partial from step t-1 (pre-wait, off critical path)
        if (t > 0 && tid < 4) {
            float s = 0.0f;
#pragma unroll
            for (int w = 0; w < 8; w++) s += osum[w * 4 + tid];
            racc += s;
            g_part[(b0 + tid) * (CSZ * L_) + c * L_ + (t - 1)] = racc;
        }

        // wait for h(t) remote slices (skip t=0: zeros written locally)
        if (t > 0) {
            mbar_wait_cta(smem_u32 + MBAR_BYTE + cur * 8, (phases >> cur) & 1u);
            phases ^= (1u << cur);
            // re-post expect for this buffer's NEXT fill round (at step t+2)
            if (tid == 256)
                mbar_expect_tx(smem_u32 + MBAR_BYTE + cur * 8, STEP_TX);
        }

        const float* hc = hbuf + cur * (D_ * ROWS);

        // ---- matvec: R from registers, h broadcast from smem ----
        {
            const ulonglong2* hvp = (const ulonglong2*)(hc + ks * KROWS * ROWS);
            unsigned long long a00 = 0, a01 = 0, a10 = 0, a11 = 0;
#pragma unroll
            for (int ii = 0; ii < KROWS; ii++) {
                ulonglong2 hv = hvp[ii];
                unsigned long long r0 = pk2(rx[ii], rx[ii]);
                unsigned long long r1 = pk2(ry[ii], ry[ii]);
                fma2(a00, r0, hv.x); fma2(a01, r0, hv.y);
                fma2(a10, r1, hv.x); fma2(a11, r1, hv.y);
            }
            float4 q0, q1;
            upk2(q0.x, q0.y, a00); upk2(q0.z, q0.w, a01);
            upk2(q1.x, q1.y, a10); upk2(q1.z, q1.w, a11);
            float* pb = pbuf + (ks * 32 + jp) * 8;
            *(float4*)(pb)     = q0;
            *(float4*)(pb + 4) = q1;
        }
        __syncthreads();

        // ---- reduce + gate + update: write h(t+1) own slice locally ----
        if (tid < 256) {
            float z = bias[jj];
#pragma unroll
            for (int s = 0; s < 16; s++) z += pbuf[s * 256 + tid];
            float ig = 1.0f / (1.0f + __expf(-z));
            float u  = civ * ig;
            float hval = hc[(j0 + jj) * 4 + bb] + u;
            hbuf[nxt * (D_ * ROWS) + (j0 + jj) * 4 + bb] = hval;

            float pp = u * wsl[jj];
            pp += __shfl_xor_sync(0xFFFFFFFF, pp, 4);
            pp += __shfl_xor_sync(0xFFFFFFFF, pp, 8);
            pp += __shfl_xor_sync(0xFFFFFFFF, pp, 16);
            if ((tid & 31) < 4)
                osum[(tid >> 5) * 4 + bb] = pp;
        }
        __syncthreads();

        // ---- DMA h(t+1) own slice to the 7 REMOTE peers (skip self) ----
        if (t + 1 < L_ && tid < CSZ && tid != c) {
            fence_proxy_async_cta();
            uint32_t off  = (uint32_t)(HBUF_OFF + nxt * (D_ * ROWS) + j0 * 4) * 4u;
            uint32_t moff = (uint32_t)(MBAR_BYTE + nxt * 8);
            bulk_dsmem(peer_base[tid] + off, smem_u32 + off, SLICE_BYTES,
                       peer_base[tid] + moff);
        }

        cur = nxt;
    }

    // final deferred output partial (t = L-1)
    if (tid < 4) {
        float s = 0.0f;
#pragma unroll
        for (int w = 0; w < 8; w++) s += osum[w * 4 + tid];
        racc += s;
        g_part[(b0 + tid) * (CSZ * L_) + c * L_ + (L_ - 1)] = racc;
    }

    asm volatile("barrier.cluster.arrive.aligned;" ::: "memory");
    asm volatile("barrier.cluster.wait.aligned;"   ::: "memory");
}

// ============================================================================
// Kernel 3: out[b,t] = b_out + sum_c g_part[b][c][t]
// ============================================================================
__global__ __launch_bounds__(256)
void k_out(const float* __restrict__ b_out, float* __restrict__ out)
{
    int i = blockIdx.x * 256 + threadIdx.x;
    int b = i >> 9, t = i & 511;
    float s = b_out[0];
#pragma unroll
    for (int cc = 0; cc < CSZ; cc++) s += g_part[b * (CSZ * L_) + cc * L_ + t];
    out[i] = s;
}

// ============================================================================
extern "C" void kernel_launch(void* const* d_in, const int* in_sizes, int n_in,
                              void* d_out, int out_size)
{
    const float* obs  = (const float*)d_in[0];
    const float* act  = (const float*)d_in[1];
    const float* W_ci = (const float*)d_in[2];
    const float* b_ci = (const float*)d_in[3];
    const float* R    = (const float*)d_in[4];
    const float* bg   = (const float*)d_in[5];
    const float* W_o  = (const float*)d_in[6];
    const float* b_o  = (const float*)d_in[7];
    float* out = (float*)d_out;

    k_ci<<<dim3(8, 512), 256>>>(obs, act, W_ci, b_ci);

    cudaFuncSetAttribute(k_scan, cudaFuncAttributeMaxDynamicSharedMemorySize, SMEM_BYTES);
    k_scan<<<dim3(CSZ, NCL), THREADS, SMEM_BYTES>>>(R, bg, W_o);

    k_out<<<128, 256>>>(b_o, out);
}